// round 11
// baseline (speedup 1.0000x reference)
#include <cuda_runtime.h>

// SoftDTW-variant, gamma=1, B=32, T=512, row-broadcast cost ds[i]=(x[i]-y[i])^2.
// Linear-weight domain: W(i,j) = 2^(P(i) - R(i,j)*log2e), P(i)=sum_{r<=i} ds'[r].
//   W(i,j) = W(i-1,j) + W(i-1,j-1) + c_i * W(i,j-1),  c_i = 2^(-ds'[i])
// 2 fp ops/cell, no MUFU in the loop. Boundaries (R=inf) are W=0.
// Frame bookkeeping: per-thread integer exponent k; pre-tile joint renorm
// brings all tile inputs <= 2 (overflow impossible for active lanes); single
// bit-built rescale factors (|shift|<=126 proven; dominated branches flush to
// 0 exactly); post-tile renorm clampless (mx in [~0.5, 2^16] for active).
// This round: zero divergent C++ branches in the loop — seam spin/load is one
// inline-asm block with warp-uniform internal branches (no BSSY), publish is
// predicated STS.128 + st.release (no branch), merges are selects. 128 thr,
// 4 cols/thread, 8 rows/superstep, 191 pipeline slots.

#define TLEN  512
#define BATCH 32
#define NTH   128
#define ROWS  8
#define RB    (TLEN / ROWS)      // 64 row-blocks
#define WSUP  (RB + 31)          // 95 supersteps per warp
#define SLOTS WSUP               // ring slots per seam (write-once)
#define SENT  0x7fffffff

__global__ __launch_bounds__(NTH, 1) void softdtw_kernel(const float* __restrict__ x,
                                                         const float* __restrict__ y,
                                                         float* __restrict__ out) {
    __shared__ float cs[TLEN];                       // c_i = 2^{-ds'[i]}
    __shared__ float redsum[4];
    __shared__ __align__(16) int ring[3 * SLOTS * 12]; // slot: [0..7] W, [8] k/flag, pad

    const int q    = threadIdx.x;
    const int lane = q & 31;
    const int w    = q >> 5;
    const int b    = blockIdx.x;

    // ---- prologue -----------------------------------------------------------
    const float L2E = 1.4426950408889634f;
    float4 xv = ((const float4*)(x + b * TLEN))[q];
    float4 yv = ((const float4*)(y + b * TLEN))[q];
    float e0 = (xv.x - yv.x) * (xv.x - yv.x) * L2E;
    float e1 = (xv.y - yv.y) * (xv.y - yv.y) * L2E;
    float e2 = (xv.z - yv.z) * (xv.z - yv.z) * L2E;
    float e3 = (xv.w - yv.w) * (xv.w - yv.w) * L2E;
    cs[4*q + 0] = exp2f(-e0);
    cs[4*q + 1] = exp2f(-e1);
    cs[4*q + 2] = exp2f(-e2);
    cs[4*q + 3] = exp2f(-e3);
    float mysum = (e0 + e1) + (e2 + e3);
    #pragma unroll
    for (int o = 16; o; o >>= 1) mysum += __shfl_xor_sync(0xffffffffu, mysum, o);
    if (lane == 0) redsum[w] = mysum;
    for (int sIdx = q; sIdx < 3 * SLOTS; sIdx += NTH) ring[sIdx * 12 + 8] = SENT;
    __syncthreads();
    const float P = (redsum[0] + redsum[1]) + (redsum[2] + redsum[3]);

    // shared-space byte addresses (32-bit), advanced incrementally
    const unsigned ringsa = (unsigned)__cvta_generic_to_shared(ring);
    unsigned caddr = ringsa + (unsigned)(((w - 1) * SLOTS + 31) * 48);  // consumer slot ts+31
    unsigned paddr = ringsa + (unsigned)((w * SLOTS) * 48);            // producer slot ts
    const int seam_base = (w > 0);
    const int pub_base  = (lane == 31) && (w < 3);

    // ---- state --------------------------------------------------------------
    float u0 = 0.f, u1 = 0.f, u2 = 0.f, u3 = 0.f;   // up-carries, frame k
    float nb0=0.f,nb1=0.f,nb2=0.f,nb3=0.f,nb4=0.f,nb5=0.f,nb6=0.f,nb7=0.f; // frame kold
    float dgW = (q == 0) ? 1.0f : 0.0f;             // diag input, frame k
    int   k = 0, kold = 0;

    for (int ts = 0; ts < WSUP; ++ts) {
        // ---- receive left boundary (8 rows) + producer frame ----
        float l0 = __shfl_up_sync(0xffffffffu, nb0, 1);
        float l1 = __shfl_up_sync(0xffffffffu, nb1, 1);
        float l2 = __shfl_up_sync(0xffffffffu, nb2, 1);
        float l3 = __shfl_up_sync(0xffffffffu, nb3, 1);
        float l4 = __shfl_up_sync(0xffffffffu, nb4, 1);
        float l5 = __shfl_up_sync(0xffffffffu, nb5, 1);
        float l6 = __shfl_up_sync(0xffffffffu, nb6, 1);
        float l7 = __shfl_up_sync(0xffffffffu, nb7, 1);
        int   kp = __shfl_up_sync(0xffffffffu, kold, 1);

        // seam: warp-uniform spin + v4 loads, all inside one asm block (no BSSY)
        float rv0=0.f,rv1=0.f,rv2=0.f,rv3=0.f,rv4=0.f,rv5=0.f,rv6=0.f,rv7=0.f;
        int kv = k;
        const int seam = seam_base & (ts < RB);
        asm volatile(
            "{\n\t"
            ".reg .pred p;\n\t"
            "setp.eq.s32 p, %10, 0;\n\t"
            "@p bra SKIP_%=;\n\t"
            "POLL_%=:\n\t"
            "ld.acquire.cta.shared.b32 %8, [%9+32];\n\t"
            "setp.eq.s32 p, %8, 2147483647;\n\t"
            "@p bra POLL_%=;\n\t"
            "ld.shared.v4.f32 {%0,%1,%2,%3}, [%9];\n\t"
            "ld.shared.v4.f32 {%4,%5,%6,%7}, [%9+16];\n\t"
            "SKIP_%=:\n\t"
            "}"
            : "+f"(rv0),"+f"(rv1),"+f"(rv2),"+f"(rv3),
              "+f"(rv4),"+f"(rv5),"+f"(rv6),"+f"(rv7),"+r"(kv)
            : "r"(caddr), "r"(seam) : "memory");
        caddr += 48;

        // branch-free lane-0 merge
        const bool z = (lane == 0);
        l0 = z ? rv0 : l0;  l1 = z ? rv1 : l1;  l2 = z ? rv2 : l2;  l3 = z ? rv3 : l3;
        l4 = z ? rv4 : l4;  l5 = z ? rv5 : l5;  l6 = z ? rv6 : l6;  l7 = z ? rv7 : l7;
        kp = z ? kv  : kp;

        const bool act = (unsigned)(ts - lane) < (unsigned)RB;

        // ---- pre-tile joint renorm (all tile inputs -> <= 2) ----
        const int dk = kp - k;
        float mlx = fmaxf(fmaxf(fmaxf(l0, l1), fmaxf(l2, l3)),
                          fmaxf(fmaxf(l4, l5), fmaxf(l6, l7)));
        const int el = ((__float_as_int(mlx) >> 23) - 127) + dk;
        const int s  = el > 0 ? el : 0;
        const int kt = k + s;                        // tile frame
        int hl = dk - s;                             // proven <= 126 for active
        hl = hl > 126 ? 126 : hl;
        const float fa = (hl < -126) ? 0.0f : __int_as_float((hl + 127) << 23);
        l0 *= fa; l1 *= fa; l2 *= fa; l3 *= fa;
        l4 *= fa; l5 *= fa; l6 *= fa; l7 *= fa;
        const float uf = (s > 126) ? 0.0f : __int_as_float((127 - s) << 23);
        float p0 = u0 * uf, p1 = u1 * uf, p2 = u2 * uf, p3 = u3 * uf;
        float dl = dgW * uf;

        // ---- row costs (address independent of the chain; LDS hidden) ----
        int ridx = ts - lane;
        ridx = ridx < 0 ? 0 : (ridx > RB - 1 ? RB - 1 : ridx);
        const float4 ca = *(const float4*)&cs[ROWS * ridx];
        const float4 cb = *(const float4*)&cs[ROWS * ridx + 4];

        // ---- 32 cells: W = (up + dg) + c * left ----
        float tn0, tn1, tn2, tn3, tn4, tn5, tn6, tn7;
        #define ROWSTEP(cr, lv, outv)                                   \
            {                                                           \
                const float a0 = p0 + dl;                               \
                const float a1 = p1 + p0;                               \
                const float a2 = p2 + p1;                               \
                const float a3 = p3 + p2;                               \
                const float q0 = fmaf(cr, lv, a0);                      \
                const float q1 = fmaf(cr, q0, a1);                      \
                const float q2 = fmaf(cr, q1, a2);                      \
                const float q3 = fmaf(cr, q2, a3);                      \
                outv = q3; dl = lv;                                     \
                p0 = q0; p1 = q1; p2 = q2; p3 = q3;                     \
            }
        ROWSTEP(ca.x, l0, tn0)
        ROWSTEP(ca.y, l1, tn1)
        ROWSTEP(ca.z, l2, tn2)
        ROWSTEP(ca.w, l3, tn3)
        ROWSTEP(cb.x, l4, tn4)
        ROWSTEP(cb.y, l5, tn5)
        ROWSTEP(cb.z, l6, tn6)
        ROWSTEP(cb.w, l7, tn7)
        #undef ROWSTEP

        // ---- post-tile renorm (clampless: active mx in [~0.5, 2^16]) ----
        const float mx = fmaxf(fmaxf(p0, p1), fmaxf(p2, p3));
        const int e = (__float_as_int(mx) >> 23) - 127;
        const float g = __int_as_float((127 - e) << 23);

        // ---- commit (active window only; predicated) ----
        if (act) {
            u0 = p0 * g; u1 = p1 * g; u2 = p2 * g; u3 = p3 * g;
            dgW = l7 * g;
            k = kt + e;
            nb0 = tn0; nb1 = tn1; nb2 = tn2; nb3 = tn3;
            nb4 = tn4; nb5 = tn5; nb6 = tn6; nb7 = tn7;   // frame kt
            kold = kt;
        }

        // ---- publish: predicated stores, no branch ----
        asm volatile(
            "{\n\t"
            ".reg .pred p;\n\t"
            "setp.ne.s32 p, %9, 0;\n\t"
            "@p st.shared.v4.f32 [%8], {%0,%1,%2,%3};\n\t"
            "@p st.shared.v4.f32 [%8+16], {%4,%5,%6,%7};\n\t"
            "@p st.release.cta.shared.b32 [%8+32], %10;\n\t"
            "}"
            :: "f"(nb0),"f"(nb1),"f"(nb2),"f"(nb3),
               "f"(nb4),"f"(nb5),"f"(nb6),"f"(nb7),
               "r"(paddr), "r"(pub_base), "r"(kold) : "memory");
        paddr += 48;
    }

    if (q == NTH - 1) {
        // R(T,T)*log2e = P - k - log2(W_raw); unscale by ln2; mean over batches.
        float Rl2 = P - (float)k - __log2f(u3);
        atomicAdd(out, Rl2 * 0.6931471805599453f * (1.0f / BATCH));
    }
}

extern "C" void kernel_launch(void* const* d_in, const int* in_sizes, int n_in,
                              void* d_out, int out_size) {
    const float* x = (const float*)d_in[0];
    const float* y = (const float*)d_in[1];
    cudaMemsetAsync(d_out, 0, sizeof(float));
    softdtw_kernel<<<BATCH, NTH>>>(x, y, (float*)d_out);
}

// round 12
// speedup vs baseline: 1.2403x; 1.2403x over previous
#include <cuda_runtime.h>

// SoftDTW-variant, gamma=1, B=32, T=512, row-broadcast cost ds[i]=(x[i]-y[i])^2.
// Linear-weight domain: W(i,j) = 2^(P(i) - R(i,j)*log2e), P(i)=sum_{r<=i} ds'[r].
//   W(i,j) = W(i-1,j) + W(i-1,j-1) + c_i * W(i,j-1),  c_i = 2^(-ds'[i]) <= 1
// 2 fp ops/cell, no MUFU in loop. Boundaries (R=inf) are W=0.
//
// R11 scheme: NO commit guard (idle lanes compute exact zeros; frame drift is
// reconciled through dk at activation), and NO post-tile renorm (u committed
// raw, bounded <= 2^14 by the tile path-count bound; its exponent is folded
// into the next superstep's joint pre-renorm s = max(el, eu, 0)).
// 128 thr, 4 cols/thread, 8 rows/superstep, 191 pipeline slots; shfl intra-warp
// handoff, release/acquire write-once smem ring inter-warp; loop is branch-free
// C++ (seam + publish in asm with warp-uniform internal branches).

#define TLEN  512
#define BATCH 32
#define NTH   128
#define ROWS  8
#define RB    (TLEN / ROWS)      // 64 row-blocks
#define WSUP  (RB + 31)          // 95 supersteps per warp
#define SLOTS WSUP
#define SENT  0x7fffffff

__global__ __launch_bounds__(NTH, 1) void softdtw_kernel(const float* __restrict__ x,
                                                         const float* __restrict__ y,
                                                         float* __restrict__ out) {
    __shared__ float cs[TLEN];                         // c_i = 2^{-ds'[i]}
    __shared__ float redsum[4];
    __shared__ __align__(16) int ring[3 * SLOTS * 12]; // slot: [0..7] W, [8] k/flag, pad

    const int q    = threadIdx.x;
    const int lane = q & 31;
    const int w    = q >> 5;
    const int b    = blockIdx.x;

    // ---- prologue -----------------------------------------------------------
    const float L2E = 1.4426950408889634f;
    float4 xv = ((const float4*)(x + b * TLEN))[q];
    float4 yv = ((const float4*)(y + b * TLEN))[q];
    float e0 = (xv.x - yv.x) * (xv.x - yv.x) * L2E;
    float e1 = (xv.y - yv.y) * (xv.y - yv.y) * L2E;
    float e2 = (xv.z - yv.z) * (xv.z - yv.z) * L2E;
    float e3 = (xv.w - yv.w) * (xv.w - yv.w) * L2E;
    cs[4*q + 0] = exp2f(-e0);
    cs[4*q + 1] = exp2f(-e1);
    cs[4*q + 2] = exp2f(-e2);
    cs[4*q + 3] = exp2f(-e3);
    float mysum = (e0 + e1) + (e2 + e3);
    #pragma unroll
    for (int o = 16; o; o >>= 1) mysum += __shfl_xor_sync(0xffffffffu, mysum, o);
    if (lane == 0) redsum[w] = mysum;
    for (int sIdx = q; sIdx < 3 * SLOTS; sIdx += NTH) ring[sIdx * 12 + 8] = SENT;
    __syncthreads();
    const float P = (redsum[0] + redsum[1]) + (redsum[2] + redsum[3]);

    const unsigned ringsa = (unsigned)__cvta_generic_to_shared(ring);
    unsigned caddr = ringsa + (unsigned)(((w - 1) * SLOTS + 31) * 48);  // consumer: slot ts+31
    unsigned paddr = ringsa + (unsigned)((w * SLOTS) * 48);            // producer: slot ts
    const int seam_base = (w > 0);
    const int pub_base  = (lane == 31) && (w < 3);

    // ---- state --------------------------------------------------------------
    float u0 = 0.f, u1 = 0.f, u2 = 0.f, u3 = 0.f;   // up-carries, RAW in frame k (<= 2^14)
    float nb0=0.f,nb1=0.f,nb2=0.f,nb3=0.f,nb4=0.f,nb5=0.f,nb6=0.f,nb7=0.f; // frame k
    float dgW = (q == 0) ? 1.0f : 0.0f;             // diag input (<= 2), frame k
    int   k = 0;

    for (int ts = 0; ts < WSUP; ++ts) {
        // ---- receive left boundary (8 rows) + producer frame ----
        float l0 = __shfl_up_sync(0xffffffffu, nb0, 1);
        float l1 = __shfl_up_sync(0xffffffffu, nb1, 1);
        float l2 = __shfl_up_sync(0xffffffffu, nb2, 1);
        float l3 = __shfl_up_sync(0xffffffffu, nb3, 1);
        float l4 = __shfl_up_sync(0xffffffffu, nb4, 1);
        float l5 = __shfl_up_sync(0xffffffffu, nb5, 1);
        float l6 = __shfl_up_sync(0xffffffffu, nb6, 1);
        float l7 = __shfl_up_sync(0xffffffffu, nb7, 1);
        int   kp = __shfl_up_sync(0xffffffffu, k,  1);

        // seam: warp-uniform spin + v4 loads inside one asm block (no BSSY)
        float rv0=0.f,rv1=0.f,rv2=0.f,rv3=0.f,rv4=0.f,rv5=0.f,rv6=0.f,rv7=0.f;
        int kv = k;
        const int seam = seam_base & (ts < RB);
        asm volatile(
            "{\n\t"
            ".reg .pred p;\n\t"
            "setp.eq.s32 p, %10, 0;\n\t"
            "@p bra SKIP_%=;\n\t"
            "POLL_%=:\n\t"
            "ld.acquire.cta.shared.b32 %8, [%9+32];\n\t"
            "setp.eq.s32 p, %8, 2147483647;\n\t"
            "@p bra POLL_%=;\n\t"
            "ld.shared.v4.f32 {%0,%1,%2,%3}, [%9];\n\t"
            "ld.shared.v4.f32 {%4,%5,%6,%7}, [%9+16];\n\t"
            "SKIP_%=:\n\t"
            "}"
            : "+f"(rv0),"+f"(rv1),"+f"(rv2),"+f"(rv3),
              "+f"(rv4),"+f"(rv5),"+f"(rv6),"+f"(rv7),"+r"(kv)
            : "r"(caddr), "r"(seam) : "memory");
        caddr += 48;

        const bool z = (lane == 0);
        l0 = z ? rv0 : l0;  l1 = z ? rv1 : l1;  l2 = z ? rv2 : l2;  l3 = z ? rv3 : l3;
        l4 = z ? rv4 : l4;  l5 = z ? rv5 : l5;  l6 = z ? rv6 : l6;  l7 = z ? rv7 : l7;
        kp = z ? kv  : kp;

        // ---- joint pre-tile renorm: all tile inputs -> <= 2 ----
        const int dk = kp - k;
        const float mlx = fmaxf(fmaxf(fmaxf(l0, l1), fmaxf(l2, l3)),
                                fmaxf(fmaxf(l4, l5), fmaxf(l6, l7)));
        const float mxu = fmaxf(fmaxf(u0, u1), fmaxf(u2, u3));
        const int el = ((__float_as_int(mlx) >> 23) - 127) + dk;  // exp of max l in frame k
        const int eu = (__float_as_int(mxu) >> 23) - 127;         // exp of max u (raw)
        int s = el > eu ? el : eu;
        s = s > 0 ? s : 0;
        const int kt = k + s;                        // tile frame
        int hl = dk - s;                             // l -> tile frame (l*fa <= 2 proven)
        hl = hl > 126 ? 126 : hl;
        const float fa = (hl < -126) ? 0.0f : __int_as_float((hl + 127) << 23);
        const float uf = (s > 126) ? 0.0f : __int_as_float((127 - s) << 23);
        l0 *= fa; l1 *= fa; l2 *= fa; l3 *= fa;
        l4 *= fa; l5 *= fa; l6 *= fa; l7 *= fa;
        float p0 = u0 * uf, p1 = u1 * uf, p2 = u2 * uf, p3 = u3 * uf;
        float dl = dgW * uf;

        // ---- row costs (chain-independent address; LDS latency hidden) ----
        int ridx = ts - lane;
        ridx = ridx < 0 ? 0 : (ridx > RB - 1 ? RB - 1 : ridx);
        const float4 ca = *(const float4*)&cs[ROWS * ridx];
        const float4 cb = *(const float4*)&cs[ROWS * ridx + 4];

        // ---- 32 cells: W = (up + dg) + c * left; outputs ARE next nb/u ----
        #define ROWSTEP(cr, lv, outv)                                   \
            {                                                           \
                const float a0 = p0 + dl;                               \
                const float a1 = p1 + p0;                               \
                const float a2 = p2 + p1;                               \
                const float a3 = p3 + p2;                               \
                const float q0 = fmaf(cr, lv, a0);                      \
                const float q1 = fmaf(cr, q0, a1);                      \
                const float q2 = fmaf(cr, q1, a2);                      \
                const float q3 = fmaf(cr, q2, a3);                      \
                outv = q3; dl = lv;                                     \
                p0 = q0; p1 = q1; p2 = q2; p3 = q3;                     \
            }
        ROWSTEP(ca.x, l0, nb0)
        ROWSTEP(ca.y, l1, nb1)
        ROWSTEP(ca.z, l2, nb2)
        ROWSTEP(ca.w, l3, nb3)
        ROWSTEP(cb.x, l4, nb4)
        ROWSTEP(cb.y, l5, nb5)
        ROWSTEP(cb.z, l6, nb6)
        ROWSTEP(cb.w, l7, nb7)
        #undef ROWSTEP

        // ---- commit: raw, no guard, no post-renorm ----
        u0 = p0; u1 = p1; u2 = p2; u3 = p3;
        dgW = dl;                                    // = scaled l7, <= 2, frame kt
        k = kt;

        // ---- publish: predicated stores, no branch ----
        asm volatile(
            "{\n\t"
            ".reg .pred p;\n\t"
            "setp.ne.s32 p, %9, 0;\n\t"
            "@p st.shared.v4.f32 [%8], {%0,%1,%2,%3};\n\t"
            "@p st.shared.v4.f32 [%8+16], {%4,%5,%6,%7};\n\t"
            "@p st.release.cta.shared.b32 [%8+32], %10;\n\t"
            "}"
            :: "f"(nb0),"f"(nb1),"f"(nb2),"f"(nb3),
               "f"(nb4),"f"(nb5),"f"(nb6),"f"(nb7),
               "r"(paddr), "r"(pub_base), "r"(k) : "memory");
        paddr += 48;
    }

    if (q == NTH - 1) {
        // R(T,T)*log2e = P - k - log2(W_raw); unscale by ln2; mean over batches.
        float Rl2 = P - (float)k - __log2f(u3);
        atomicAdd(out, Rl2 * 0.6931471805599453f * (1.0f / BATCH));
    }
}

extern "C" void kernel_launch(void* const* d_in, const int* in_sizes, int n_in,
                              void* d_out, int out_size) {
    const float* x = (const float*)d_in[0];
    const float* y = (const float*)d_in[1];
    cudaMemsetAsync(d_out, 0, sizeof(float));
    softdtw_kernel<<<BATCH, NTH>>>(x, y, (float*)d_out);
}

// round 13
// speedup vs baseline: 1.4463x; 1.1661x over previous
#include <cuda_runtime.h>

// SoftDTW-variant, gamma=1, B=32, T=512, row-broadcast cost ds[i]=(x[i]-y[i])^2.
// Linear-weight domain: W(i,j) = 2^(P(i) - R(i,j)*log2e), P(i)=sum_{r<=i} ds'[r].
//   W(i,j) = W(i-1,j) + W(i-1,j-1) + c_i * W(i,j-1),  c_i = 2^(-ds'[i]) <= 1
// 2 fp ops/cell, no MUFU in loop. Boundaries (R=inf) are W=0.
//
// R12 scheme (guard-free commits, raw u, joint pre-tile renorm) retained.
// This round: 2 warps per batch, 8 columns/lane, 8 rows/superstep ->
// wall slots = 64 + 31 + 32 = 127 (was 191), single seam, double per-slot
// tile work rides inside the latency bubbles (we were at 26% issue).

#define TLEN  512
#define BATCH 32
#define NTH   64
#define ROWS  8
#define COLS  8                   // columns per lane
#define RB    (TLEN / ROWS)       // 64 row-blocks
#define WSUP  (RB + 31)           // 95 supersteps per warp
#define SLOTS WSUP
#define SENT  0x7fffffff

__global__ __launch_bounds__(NTH, 1) void softdtw_kernel(const float* __restrict__ x,
                                                         const float* __restrict__ y,
                                                         float* __restrict__ out) {
    __shared__ float cs[TLEN];                      // c_i = 2^{-ds'[i]}
    __shared__ float redsum[2];
    __shared__ __align__(16) int ring[SLOTS * 12];  // one seam: [0..7] W, [8] k/flag, pad

    const int q    = threadIdx.x;
    const int lane = q & 31;
    const int w    = q >> 5;
    const int b    = blockIdx.x;

    // ---- prologue: 8 costs per thread ---------------------------------------
    const float L2E = 1.4426950408889634f;
    float4 xa = ((const float4*)(x + b * TLEN))[2 * q];
    float4 xb = ((const float4*)(x + b * TLEN))[2 * q + 1];
    float4 ya = ((const float4*)(y + b * TLEN))[2 * q];
    float4 yb = ((const float4*)(y + b * TLEN))[2 * q + 1];
    float e0 = (xa.x - ya.x) * (xa.x - ya.x) * L2E;
    float e1 = (xa.y - ya.y) * (xa.y - ya.y) * L2E;
    float e2 = (xa.z - ya.z) * (xa.z - ya.z) * L2E;
    float e3 = (xa.w - ya.w) * (xa.w - ya.w) * L2E;
    float e4 = (xb.x - yb.x) * (xb.x - yb.x) * L2E;
    float e5 = (xb.y - yb.y) * (xb.y - yb.y) * L2E;
    float e6 = (xb.z - yb.z) * (xb.z - yb.z) * L2E;
    float e7 = (xb.w - yb.w) * (xb.w - yb.w) * L2E;
    cs[8*q + 0] = exp2f(-e0);  cs[8*q + 1] = exp2f(-e1);
    cs[8*q + 2] = exp2f(-e2);  cs[8*q + 3] = exp2f(-e3);
    cs[8*q + 4] = exp2f(-e4);  cs[8*q + 5] = exp2f(-e5);
    cs[8*q + 6] = exp2f(-e6);  cs[8*q + 7] = exp2f(-e7);
    float mysum = ((e0 + e1) + (e2 + e3)) + ((e4 + e5) + (e6 + e7));
    #pragma unroll
    for (int o = 16; o; o >>= 1) mysum += __shfl_xor_sync(0xffffffffu, mysum, o);
    if (lane == 0) redsum[w] = mysum;
    for (int sIdx = q; sIdx < SLOTS; sIdx += NTH) ring[sIdx * 12 + 8] = SENT;
    __syncthreads();
    const float P = redsum[0] + redsum[1];

    const unsigned ringsa = (unsigned)__cvta_generic_to_shared(ring);
    unsigned caddr = ringsa + 31u * 48u;            // consumer (warp1): slot ts+31
    unsigned paddr = ringsa;                        // producer (warp0 lane31): slot ts
    const int seam_base = (w == 1);
    const int pub_base  = (lane == 31) && (w == 0);

    // ---- state --------------------------------------------------------------
    float u0=0.f,u1=0.f,u2=0.f,u3=0.f,u4=0.f,u5=0.f,u6=0.f,u7=0.f; // col carries, RAW, frame k
    float nb0=0.f,nb1=0.f,nb2=0.f,nb3=0.f,nb4=0.f,nb5=0.f,nb6=0.f,nb7=0.f; // boundary, frame k
    float dgW = (q == 0) ? 1.0f : 0.0f;             // diag input (<= 2), frame k
    int   k = 0;

    for (int ts = 0; ts < WSUP; ++ts) {
        // ---- receive left boundary (8 rows) + producer frame ----
        float l0 = __shfl_up_sync(0xffffffffu, nb0, 1);
        float l1 = __shfl_up_sync(0xffffffffu, nb1, 1);
        float l2 = __shfl_up_sync(0xffffffffu, nb2, 1);
        float l3 = __shfl_up_sync(0xffffffffu, nb3, 1);
        float l4 = __shfl_up_sync(0xffffffffu, nb4, 1);
        float l5 = __shfl_up_sync(0xffffffffu, nb5, 1);
        float l6 = __shfl_up_sync(0xffffffffu, nb6, 1);
        float l7 = __shfl_up_sync(0xffffffffu, nb7, 1);
        int   kp = __shfl_up_sync(0xffffffffu, k,  1);

        // seam: warp-uniform spin + v4 loads inside one asm block (no BSSY)
        float rv0=0.f,rv1=0.f,rv2=0.f,rv3=0.f,rv4=0.f,rv5=0.f,rv6=0.f,rv7=0.f;
        int kv = k;
        const int seam = seam_base & (ts < RB);
        asm volatile(
            "{\n\t"
            ".reg .pred p;\n\t"
            "setp.eq.s32 p, %10, 0;\n\t"
            "@p bra SKIP_%=;\n\t"
            "POLL_%=:\n\t"
            "ld.acquire.cta.shared.b32 %8, [%9+32];\n\t"
            "setp.eq.s32 p, %8, 2147483647;\n\t"
            "@p bra POLL_%=;\n\t"
            "ld.shared.v4.f32 {%0,%1,%2,%3}, [%9];\n\t"
            "ld.shared.v4.f32 {%4,%5,%6,%7}, [%9+16];\n\t"
            "SKIP_%=:\n\t"
            "}"
            : "+f"(rv0),"+f"(rv1),"+f"(rv2),"+f"(rv3),
              "+f"(rv4),"+f"(rv5),"+f"(rv6),"+f"(rv7),"+r"(kv)
            : "r"(caddr), "r"(seam) : "memory");
        caddr += 48;

        const bool z = (lane == 0);
        l0 = z ? rv0 : l0;  l1 = z ? rv1 : l1;  l2 = z ? rv2 : l2;  l3 = z ? rv3 : l3;
        l4 = z ? rv4 : l4;  l5 = z ? rv5 : l5;  l6 = z ? rv6 : l6;  l7 = z ? rv7 : l7;
        kp = z ? kv  : kp;

        // ---- joint pre-tile renorm: all tile inputs -> <= 2 ----
        const int dk = kp - k;
        const float mlx = fmaxf(fmaxf(fmaxf(l0, l1), fmaxf(l2, l3)),
                                fmaxf(fmaxf(l4, l5), fmaxf(l6, l7)));
        const float mxu = fmaxf(fmaxf(fmaxf(u0, u1), fmaxf(u2, u3)),
                                fmaxf(fmaxf(u4, u5), fmaxf(u6, u7)));
        const int el = ((__float_as_int(mlx) >> 23) - 127) + dk;
        const int eu = (__float_as_int(mxu) >> 23) - 127;
        int s = el > eu ? el : eu;
        s = s > 0 ? s : 0;
        const int kt = k + s;                       // tile frame
        int hl = dk - s;
        hl = hl > 126 ? 126 : hl;
        const float fa = (hl < -126) ? 0.0f : __int_as_float((hl + 127) << 23);
        const float uf = (s > 126) ? 0.0f : __int_as_float((127 - s) << 23);
        l0 *= fa; l1 *= fa; l2 *= fa; l3 *= fa;
        l4 *= fa; l5 *= fa; l6 *= fa; l7 *= fa;
        float p0 = u0 * uf, p1 = u1 * uf, p2 = u2 * uf, p3 = u3 * uf;
        float p4 = u4 * uf, p5 = u5 * uf, p6 = u6 * uf, p7 = u7 * uf;
        float dl = dgW * uf;

        // ---- row costs (chain-independent address) ----
        int ridx = ts - lane;
        ridx = ridx < 0 ? 0 : (ridx > RB - 1 ? RB - 1 : ridx);
        const float4 ca = *(const float4*)&cs[ROWS * ridx];
        const float4 cb = *(const float4*)&cs[ROWS * ridx + 4];

        // ---- 64 cells: W(i,j) = (up_j + up_{j-1}) + c_i * left ----
        #define ROWSTEP(cr, lv, outv)                                       \
            {                                                               \
                const float a0 = p0 + dl;  const float a1 = p1 + p0;        \
                const float a2 = p2 + p1;  const float a3 = p3 + p2;        \
                const float a4 = p4 + p3;  const float a5 = p5 + p4;        \
                const float a6 = p6 + p5;  const float a7 = p7 + p6;        \
                const float t0 = fmaf(cr, lv, a0);                          \
                const float t1 = fmaf(cr, t0, a1);                          \
                const float t2 = fmaf(cr, t1, a2);                          \
                const float t3 = fmaf(cr, t2, a3);                          \
                const float t4 = fmaf(cr, t3, a4);                          \
                const float t5 = fmaf(cr, t4, a5);                          \
                const float t6 = fmaf(cr, t5, a6);                          \
                const float t7 = fmaf(cr, t6, a7);                          \
                outv = t7; dl = lv;                                         \
                p0 = t0; p1 = t1; p2 = t2; p3 = t3;                         \
                p4 = t4; p5 = t5; p6 = t6; p7 = t7;                         \
            }
        ROWSTEP(ca.x, l0, nb0)
        ROWSTEP(ca.y, l1, nb1)
        ROWSTEP(ca.z, l2, nb2)
        ROWSTEP(ca.w, l3, nb3)
        ROWSTEP(cb.x, l4, nb4)
        ROWSTEP(cb.y, l5, nb5)
        ROWSTEP(cb.z, l6, nb6)
        ROWSTEP(cb.w, l7, nb7)
        #undef ROWSTEP

        // ---- commit: raw, no guard, no post-renorm ----
        u0 = p0; u1 = p1; u2 = p2; u3 = p3;
        u4 = p4; u5 = p5; u6 = p6; u7 = p7;
        dgW = dl;                                   // frame kt
        k = kt;

        // ---- publish (warp0 lane31): predicated stores, no branch ----
        asm volatile(
            "{\n\t"
            ".reg .pred p;\n\t"
            "setp.ne.s32 p, %9, 0;\n\t"
            "@p st.shared.v4.f32 [%8], {%0,%1,%2,%3};\n\t"
            "@p st.shared.v4.f32 [%8+16], {%4,%5,%6,%7};\n\t"
            "@p st.release.cta.shared.b32 [%8+32], %10;\n\t"
            "}"
            :: "f"(nb0),"f"(nb1),"f"(nb2),"f"(nb3),
               "f"(nb4),"f"(nb5),"f"(nb6),"f"(nb7),
               "r"(paddr), "r"(pub_base), "r"(k) : "memory");
        paddr += 48;
    }

    if (q == NTH - 1) {
        // R(T,T)*log2e = P - k - log2(W_raw); unscale by ln2; mean over batches.
        float Rl2 = P - (float)k - __log2f(u7);
        atomicAdd(out, Rl2 * 0.6931471805599453f * (1.0f / BATCH));
    }
}

extern "C" void kernel_launch(void* const* d_in, const int* in_sizes, int n_in,
                              void* d_out, int out_size) {
    const float* x = (const float*)d_in[0];
    const float* y = (const float*)d_in[1];
    cudaMemsetAsync(d_out, 0, sizeof(float));
    softdtw_kernel<<<BATCH, NTH>>>(x, y, (float*)d_out);
}